// round 16
// baseline (speedup 1.0000x reference)
#include <cuda_runtime.h>
#include <cuda_bf16.h>
#include <cstdint>

#define NND 50000
#define NE  800000
#define HD  128          // H*D
#define NH  4
#define INDIM 256
#define MT 64            // rows per GEMM CTA
#define NGRID ((NND + MT - 1) / MT)   // 782
#define NB 196           // scan blocks

// ---------------- scratch (no allocations allowed) ----------------
__device__ float    g_el[(size_t)NND * HD];
__device__ float    g_er[(size_t)NND * HD];
__device__ float    g_scores[(size_t)NE * NH];
__device__ float2   g_mden[(size_t)NND * NH];
__device__ int      g_cnt[NND];
__device__ int      g_off[NND + 1];
__device__ int      g_cursor[NND];
__device__ int2     g_pairs[NE];
__device__ int      g_bsum[NB];
__device__ int      g_bpref[NB];
__device__ unsigned g_Wtb32[16 * 256 * 8];   // big    (128 KB)
__device__ unsigned g_Wts32[16 * 256 * 8];   // small  (128 KB)

__device__ __forceinline__ float lrelu(float x) { return x > 0.f ? x : 0.2f * x; }

__device__ __forceinline__ unsigned bfpair(float lo, float hi) {
    unsigned ul = (unsigned)__bfloat16_as_ushort(__float2bfloat16_rn(lo));
    unsigned uh = (unsigned)__bfloat16_as_ushort(__float2bfloat16_rn(hi));
    return ul | (uh << 16);
}
__device__ __forceinline__ float bf_big(float x) {
    return __bfloat162float(__float2bfloat16_rn(x));
}

__device__ __forceinline__ void mma16816(float* c, const unsigned* a, const unsigned* b) {
    asm volatile(
        "mma.sync.aligned.m16n8k16.row.col.f32.bf16.bf16.f32 "
        "{%0,%1,%2,%3}, {%4,%5,%6,%7}, {%8,%9}, {%0,%1,%2,%3};\n"
        : "+f"(c[0]), "+f"(c[1]), "+f"(c[2]), "+f"(c[3])
        : "r"(a[0]), "r"(a[1]), "r"(a[2]), "r"(a[3]), "r"(b[0]), "r"(b[1]));
}

__device__ __forceinline__ uint32_t smem_u32(const void* p) {
    uint32_t a;
    asm("{ .reg .u64 t; cvta.to.shared.u64 t, %1; cvt.u32.u64 %0, t; }" : "=r"(a) : "l"(p));
    return a;
}
__device__ __forceinline__ void cp16(uint32_t dst, const void* src, int src_bytes) {
    asm volatile("cp.async.cg.shared.global [%0], [%1], 16, %2;"
                 :: "r"(dst), "l"(src), "r"(src_bytes) : "memory");
}
#define CP_COMMIT() asm volatile("cp.async.commit_group;" ::: "memory")
#define CP_WAIT1()  asm volatile("cp.async.wait_group 1;" ::: "memory")

// ---------------- K_wprep ----------------
__global__ void __launch_bounds__(128) k_wprep(const float* __restrict__ Ws,
                                               const float* __restrict__ Wd) {
    int n  = blockIdx.x;
    int t  = threadIdx.x;
    int ch = t >> 3;
    int w  = t & 7;
    int k  = ch * 16 + 2 * w;
    const float* W = (n < HD) ? Ws : Wd;
    int nn = n & (HD - 1);
    float v0 = W[(size_t)k * HD + nn];
    float v1 = W[(size_t)(k + 1) * HD + nn];
    float b0 = bf_big(v0), b1 = bf_big(v1);
    g_Wtb32[ch * 2048 + n * 8 + w] = bfpair(b0, b1);
    g_Wts32[ch * 2048 + n * 8 + w] = bfpair(v0 - b0, v1 - b1);
}

// ---------------- K1: split-bf16 mma.sync GEMM, cp.async 2-stage pipeline -----
__global__ void __launch_bounds__(256, 2) k_gemm(const float* __restrict__ h,
                                                 const float* __restrict__ bsrc,
                                                 const float* __restrict__ bdst) {
    __shared__ float    sA [2][64 * 16];
    __shared__ unsigned sBb[2][2048];
    __shared__ unsigned sBs[2][2048];

    const int t    = threadIdx.x;
    const int wid  = t >> 5;
    const int lane = t & 31;
    const int g    = lane >> 2;
    const int tq   = lane & 3;
    const int row0 = blockIdx.x * MT;

    const int mb    = (wid & 3) * 16;
    const int nbase = (wid >> 2) * 128;

    float acc[16][4];
    #pragma unroll
    for (int nt = 0; nt < 16; nt++)
        #pragma unroll
        for (int q = 0; q < 4; q++) acc[nt][q] = 0.f;

    const int ar = t >> 2;
    const int aq = t & 3;
    const int gr = row0 + ar;
    const float* aSrcBase = h + (size_t)gr * INDIM + aq * 4;
    const int aBytes = (gr < NND) ? 16 : 0;
    const uint32_t aDst0 = smem_u32(&sA[0][0]) + (uint32_t)(ar * 64 + ((aq ^ (ar & 3)) * 16));
    const int aStage = 64 * 16 * 4;

    const int bn  = t;
    const int bsw = (bn >> 2) & 1;
    const uint32_t bbDst0 = smem_u32(&sBb[0][0]) + (uint32_t)(bn * 32 + (0 ^ bsw) * 16);
    const uint32_t bbDst1 = smem_u32(&sBb[0][0]) + (uint32_t)(bn * 32 + (1 ^ bsw) * 16);
    const uint32_t bsDst0 = smem_u32(&sBs[0][0]) + (uint32_t)(bn * 32 + (0 ^ bsw) * 16);
    const uint32_t bsDst1 = smem_u32(&sBs[0][0]) + (uint32_t)(bn * 32 + (1 ^ bsw) * 16);
    const int bStage = 2048 * 4;

    auto issue = [&](int ch, int s) {
        if (ch < 16) {
            cp16(aDst0 + s * aStage, aSrcBase + ch * 16, aBytes);
            const unsigned* wb = g_Wtb32 + ch * 2048 + bn * 8;
            const unsigned* ws = g_Wts32 + ch * 2048 + bn * 8;
            cp16(bbDst0 + s * bStage, wb,     16);
            cp16(bbDst1 + s * bStage, wb + 4, 16);
            cp16(bsDst0 + s * bStage, ws,     16);
            cp16(bsDst1 + s * bStage, ws + 4, 16);
        }
        CP_COMMIT();
    };

    issue(0, 0);
    issue(1, 1);

    const int rlo = mb + g, rhi = rlo + 8;
    const int klo = 2 * tq;
    const int alo0 = rlo * 16 + (((klo >> 2)    ) ^ (rlo & 3)) * 4 + (klo & 3);
    const int alo8 = rlo * 16 + (((klo >> 2) + 2) ^ (rlo & 3)) * 4 + (klo & 3);
    const int ahi0 = rhi * 16 + (((klo >> 2)    ) ^ (rhi & 3)) * 4 + (klo & 3);
    const int ahi8 = rhi * 16 + (((klo >> 2) + 2) ^ (rhi & 3)) * 4 + (klo & 3);

    for (int ch = 0; ch < 16; ch++) {
        const int s = ch & 1;
        CP_WAIT1();
        __syncthreads();

        const float* A = sA[s];
        float2 vlo0 = *reinterpret_cast<const float2*>(A + alo0);
        float2 vhi0 = *reinterpret_cast<const float2*>(A + ahi0);
        float2 vlo8 = *reinterpret_cast<const float2*>(A + alo8);
        float2 vhi8 = *reinterpret_cast<const float2*>(A + ahi8);
        float b;
        unsigned ab[4], ar_[4];
        b = bf_big(vlo0.x); float b2 = bf_big(vlo0.y);
        ab[0] = bfpair(b, b2);          ar_[0] = bfpair(vlo0.x - b, vlo0.y - b2);
        b = bf_big(vhi0.x); b2 = bf_big(vhi0.y);
        ab[1] = bfpair(b, b2);          ar_[1] = bfpair(vhi0.x - b, vhi0.y - b2);
        b = bf_big(vlo8.x); b2 = bf_big(vlo8.y);
        ab[2] = bfpair(b, b2);          ar_[2] = bfpair(vlo8.x - b, vlo8.y - b2);
        b = bf_big(vhi8.x); b2 = bf_big(vhi8.y);
        ab[3] = bfpair(b, b2);          ar_[3] = bfpair(vhi8.x - b, vhi8.y - b2);

        const unsigned* Bb = sBb[s];
        const unsigned* Bs = sBs[s];
        #pragma unroll
        for (int nt = 0; nt < 16; nt++) {
            int n   = nbase + nt * 8 + g;
            int qsw = (n >> 2) & 1;
            int i0  = n * 8 + qsw * 4 + tq;
            int i1  = n * 8 + (1 ^ qsw) * 4 + tq;
            unsigned bb[2] = {Bb[i0], Bb[i1]};
            unsigned bs[2] = {Bs[i0], Bs[i1]};
            mma16816(acc[nt], ab,  bb);
            mma16816(acc[nt], ar_, bb);
            mma16816(acc[nt], ab,  bs);
        }
        __syncthreads();
        issue(ch + 2, s);
    }

    const int grl = row0 + mb + g;
    const int grh = grl + 8;
    #pragma unroll
    for (int nt = 0; nt < 16; nt++) {
        int col = nbase + nt * 8 + 2 * tq;
        float* outp = (col < HD) ? g_el : g_er;
        const float* bias = (col < HD) ? bsrc : bdst;
        int cc = col & (HD - 1);
        float2 bv = *reinterpret_cast<const float2*>(bias + cc);
        if (grl < NND)
            *reinterpret_cast<float2*>(outp + (size_t)grl * HD + cc) =
                make_float2(acc[nt][0] + bv.x, acc[nt][1] + bv.y);
        if (grh < NND)
            *reinterpret_cast<float2*>(outp + (size_t)grh * HD + cc) =
                make_float2(acc[nt][2] + bv.x, acc[nt][3] + bv.y);
    }
}

// ---------------- CSR build ----------------
__global__ void k_zero() {
    int i = blockIdx.x * blockDim.x + threadIdx.x;
    if (i < NND) g_cnt[i] = 0;
}
__global__ void k_hist(const int* __restrict__ dst) {
    int e = blockIdx.x * blockDim.x + threadIdx.x;
    if (e < NE) atomicAdd(&g_cnt[dst[e]], 1);
}

__global__ void __launch_bounds__(256) k_bsum() {
    __shared__ int s[8];
    int idx = blockIdx.x * 256 + threadIdx.x;
    int v = (idx < NND) ? g_cnt[idx] : 0;
    #pragma unroll
    for (int o = 16; o > 0; o >>= 1) v += __shfl_xor_sync(0xffffffffu, v, o);
    if ((threadIdx.x & 31) == 0) s[threadIdx.x >> 5] = v;
    __syncthreads();
    if (threadIdx.x < 8) {
        int w = s[threadIdx.x];
        #pragma unroll
        for (int o = 4; o > 0; o >>= 1) w += __shfl_xor_sync(0xffu, w, o);
        if (threadIdx.x == 0) g_bsum[blockIdx.x] = w;
    }
}

__global__ void __launch_bounds__(256) k_bscan() {
    __shared__ int s[256];
    int t = threadIdx.x;
    int v = (t < NB) ? g_bsum[t] : 0;
    s[t] = v;
    __syncthreads();
    #pragma unroll
    for (int o = 1; o < 256; o <<= 1) {
        int u = (t >= o) ? s[t - o] : 0;
        __syncthreads();
        s[t] += u;
        __syncthreads();
    }
    if (t < NB) g_bpref[t] = s[t] - v;
    if (t == 0) g_off[NND] = NE;
}

__global__ void __launch_bounds__(256) k_offsets() {
    __shared__ int s[256];
    int t   = threadIdx.x;
    int idx = blockIdx.x * 256 + t;
    int v   = (idx < NND) ? g_cnt[idx] : 0;
    s[t] = v;
    __syncthreads();
    #pragma unroll
    for (int o = 1; o < 256; o <<= 1) {
        int u = (t >= o) ? s[t - o] : 0;
        __syncthreads();
        s[t] += u;
        __syncthreads();
    }
    if (idx < NND) {
        int off = g_bpref[blockIdx.x] + s[t] - v;
        g_off[idx]    = off;
        g_cursor[idx] = off;
    }
}

__global__ void k_bucket(const int* __restrict__ src, const int* __restrict__ dst) {
    int e = blockIdx.x * blockDim.x + threadIdx.x;
    if (e >= NE) return;
    int d = dst[e];
    int p = atomicAdd(&g_cursor[d], 1);
    g_pairs[p] = make_int2(e, src[e]);
}

// ---------------- K_dst: warp-per-dst; register pairs + 6-slot el pipeline ----
__global__ void __launch_bounds__(256) k_dst(const float* __restrict__ attn,
                                             float* __restrict__ out) {
    const int d    = (blockIdx.x * 256 + threadIdx.x) >> 5;
    const int lane = threadIdx.x & 31;
    if (d >= NND) return;

    const int start = g_off[d];
    const int cnt   = g_off[d + 1] - start;

    const float4 er4 = reinterpret_cast<const float4*>(g_er + (size_t)d * HD)[lane];
    const float4 w4  = reinterpret_cast<const float4*>(attn)[lane];

    float m = -1e30f, denom = 0.f;
    float4 acc = make_float4(0.f, 0.f, 0.f, 0.f);
    const unsigned FULL = 0xffffffffu;

    for (int base = 0; base < cnt; base += 32) {
        const int nIn = min(32, cnt - base);
        // one coalesced load covers the whole chunk's pairs (lane l -> edge l)
        int2 myPair = g_pairs[start + base + ((lane < nIn) ? lane : 0)];

        // fetch el row for chunk-local edge j into (sl, eid); address via shfl
        #define FETCH(j, sl, eid) do {                                          \
            int jj = ((j) < nIn) ? (j) : 0;                                     \
            int sN = __shfl_sync(FULL, myPair.y, jj);                           \
            (eid)  = __shfl_sync(FULL, myPair.x, jj);                           \
            (sl) = reinterpret_cast<const float4*>(g_el + (size_t)sN * HD)[lane]; \
        } while (0)

        // process chunk-local edge j held in (a4, eid)
        #define PROC(j, a4, eid) do {                                           \
            if ((j) < nIn) {                                                    \
                float sc = lrelu((a4).x + er4.x) * w4.x +                       \
                           lrelu((a4).y + er4.y) * w4.y +                       \
                           lrelu((a4).z + er4.z) * w4.z +                       \
                           lrelu((a4).w + er4.w) * w4.w;                        \
                sc += __shfl_xor_sync(FULL, sc, 1);                             \
                sc += __shfl_xor_sync(FULL, sc, 2);                             \
                sc += __shfl_xor_sync(FULL, sc, 4);                             \
                if ((lane & 7) == 0)                                            \
                    g_scores[(size_t)(eid) * NH + (lane >> 3)] = sc;            \
                float delta = sc - m;                                           \
                bool  up    = delta > 0.f;                                      \
                float e     = __expf(up ? -delta : delta);                      \
                float scl   = up ? e : 1.f;                                     \
                float ex    = up ? 1.f : e;                                     \
                if (up) m = sc;                                                 \
                denom = denom * scl + ex;                                       \
                acc.x = fmaf(acc.x, scl, ex * (a4).x);                          \
                acc.y = fmaf(acc.y, scl, ex * (a4).y);                          \
                acc.z = fmaf(acc.z, scl, ex * (a4).z);                          \
                acc.w = fmaf(acc.w, scl, ex * (a4).w);                          \
            }                                                                   \
        } while (0)

        float4 s0, s1, s2, s3, s4, s5;
        int    e0, e1, e2, e3, e4, e5;
        FETCH(0, s0, e0); FETCH(1, s1, e1);
        FETCH(2, s2, e2); FETCH(3, s3, e3);
        FETCH(4, s4, e4); FETCH(5, s5, e5);

        for (int j = 0; j < nIn; j += 2) {
            PROC(j,     s0, e0);
            PROC(j + 1, s1, e1);
            // rotate: (s2,s3)->(s0,s1), (s4,s5)->(s2,s3); prefetch j+6, j+7
            s0 = s2; e0 = e2; s1 = s3; e1 = e3;
            s2 = s4; e2 = e4; s3 = s5; e3 = e5;
            FETCH(j + 6, s4, e4);
            FETCH(j + 7, s5, e5);
        }
        #undef FETCH
        #undef PROC
    }

    float rden = (cnt > 0) ? 1.f / denom : 0.f;

    float4 o4 = make_float4(acc.x * rden, acc.y * rden, acc.z * rden, acc.w * rden);
    reinterpret_cast<float4*>(out + (size_t)d * HD)[lane] = o4;

    if ((lane & 7) == 0)
        g_mden[(size_t)d * NH + (lane >> 3)] = make_float2(m, rden);
}

// ---------------- K_attn: flat edge-parallel attention weights ----------------
__global__ void __launch_bounds__(256) k_attn(const int* __restrict__ dst,
                                              float* __restrict__ out_a) {
    int i = blockIdx.x * 256 + threadIdx.x;
    if (i >= NE * NH) return;
    int e = i >> 2;
    int d = __ldg(&dst[e]);
    float2 md = g_mden[(size_t)d * NH + (i & 3)];
    out_a[i] = __expf(g_scores[i] - md.x) * md.y;
}

// ---------------- launch ----------------
extern "C" void kernel_launch(void* const* d_in, const int* in_sizes, int n_in,
                              void* d_out, int out_size) {
    const float* h     = (const float*)d_in[0];
    const int*   src   = (const int*)  d_in[1];
    const int*   dst   = (const int*)  d_in[2];
    const float* W_src = (const float*)d_in[3];
    const float* b_src = (const float*)d_in[4];
    const float* W_dst = (const float*)d_in[5];
    const float* b_dst = (const float*)d_in[6];
    const float* attn  = (const float*)d_in[7];

    float* out   = (float*)d_out;
    float* out_a = out + (size_t)NND * HD;
    int writeA   = (out_size >= NND * HD + NE * NH) ? 1 : 0;

    cudaStream_t s2;
    cudaEvent_t  evFork, evJoin;
    cudaStreamCreateWithFlags(&s2, cudaStreamNonBlocking);
    cudaEventCreateWithFlags(&evFork, cudaEventDisableTiming);
    cudaEventCreateWithFlags(&evJoin, cudaEventDisableTiming);

    cudaEventRecord(evFork, 0);
    cudaStreamWaitEvent(s2, evFork, 0);

    // side stream: start of CSR chain
    k_zero   <<<(NND + 255) / 256, 256, 0, s2>>>();
    k_hist   <<<(NE + 255) / 256, 256, 0, s2>>>(dst);
    // main stream: W prep, then GEMM (launch #4 for the ncu skip-window)
    k_wprep<<<256, 128>>>(W_src, W_dst);
    k_gemm <<<NGRID, 256>>>(h, b_src, b_dst);
    // side stream: rest of CSR chain
    k_bsum   <<<NB, 256, 0, s2>>>();
    k_bscan  <<<1, 256, 0, s2>>>();
    k_offsets<<<NB, 256, 0, s2>>>();
    k_bucket <<<(NE + 255) / 256, 256, 0, s2>>>(src, dst);
    cudaEventRecord(evJoin, s2);

    cudaStreamWaitEvent(0, evJoin, 0);
    k_dst<<<(NND * 32 + 255) / 256, 256>>>(attn, out);
    if (writeA)
        k_attn<<<(NE * NH + 255) / 256, 256>>>(dst, out_a);
}

// round 17
// speedup vs baseline: 1.2222x; 1.2222x over previous
#include <cuda_runtime.h>
#include <cuda_bf16.h>
#include <cstdint>

#define NND 50000
#define NE  800000
#define HD  128          // H*D
#define NH  4
#define INDIM 256
#define MT 64            // rows per GEMM CTA
#define NGRID ((NND + MT - 1) / MT)   // 782
#define NB 196           // scan blocks

// ---------------- scratch (no allocations allowed) ----------------
__device__ float    g_el[(size_t)NND * HD];
__device__ float    g_er[(size_t)NND * HD];
__device__ float    g_scores[(size_t)NE * NH];
__device__ float2   g_mden[(size_t)NND * NH];
__device__ int      g_cnt[NND];
__device__ int      g_off[NND + 1];
__device__ int      g_cursor[NND];
__device__ int2     g_pairs[NE];
__device__ int      g_bsum[NB];
__device__ int      g_bpref[NB];
__device__ unsigned g_Wtb32[16 * 256 * 8];   // big    (128 KB)
__device__ unsigned g_Wts32[16 * 256 * 8];   // small  (128 KB)

__device__ __forceinline__ float lrelu(float x) { return x > 0.f ? x : 0.2f * x; }

__device__ __forceinline__ unsigned bfpair(float lo, float hi) {
    unsigned ul = (unsigned)__bfloat16_as_ushort(__float2bfloat16_rn(lo));
    unsigned uh = (unsigned)__bfloat16_as_ushort(__float2bfloat16_rn(hi));
    return ul | (uh << 16);
}
__device__ __forceinline__ float bf_big(float x) {
    return __bfloat162float(__float2bfloat16_rn(x));
}

__device__ __forceinline__ void mma16816(float* c, const unsigned* a, const unsigned* b) {
    asm volatile(
        "mma.sync.aligned.m16n8k16.row.col.f32.bf16.bf16.f32 "
        "{%0,%1,%2,%3}, {%4,%5,%6,%7}, {%8,%9}, {%0,%1,%2,%3};\n"
        : "+f"(c[0]), "+f"(c[1]), "+f"(c[2]), "+f"(c[3])
        : "r"(a[0]), "r"(a[1]), "r"(a[2]), "r"(a[3]), "r"(b[0]), "r"(b[1]));
}

__device__ __forceinline__ uint32_t smem_u32(const void* p) {
    uint32_t a;
    asm("{ .reg .u64 t; cvta.to.shared.u64 t, %1; cvt.u32.u64 %0, t; }" : "=r"(a) : "l"(p));
    return a;
}
__device__ __forceinline__ void cp16(uint32_t dst, const void* src, int src_bytes) {
    asm volatile("cp.async.cg.shared.global [%0], [%1], 16, %2;"
                 :: "r"(dst), "l"(src), "r"(src_bytes) : "memory");
}
#define CP_COMMIT() asm volatile("cp.async.commit_group;" ::: "memory")
#define CP_WAIT1()  asm volatile("cp.async.wait_group 1;" ::: "memory")

// ---------------- K_wprep ----------------
__global__ void __launch_bounds__(128) k_wprep(const float* __restrict__ Ws,
                                               const float* __restrict__ Wd) {
    int n  = blockIdx.x;
    int t  = threadIdx.x;
    int ch = t >> 3;
    int w  = t & 7;
    int k  = ch * 16 + 2 * w;
    const float* W = (n < HD) ? Ws : Wd;
    int nn = n & (HD - 1);
    float v0 = W[(size_t)k * HD + nn];
    float v1 = W[(size_t)(k + 1) * HD + nn];
    float b0 = bf_big(v0), b1 = bf_big(v1);
    g_Wtb32[ch * 2048 + n * 8 + w] = bfpair(b0, b1);
    g_Wts32[ch * 2048 + n * 8 + w] = bfpair(v0 - b0, v1 - b1);
}

// ---------------- K1: split-bf16 mma.sync GEMM, cp.async 2-stage pipeline -----
__global__ void __launch_bounds__(256, 2) k_gemm(const float* __restrict__ h,
                                                 const float* __restrict__ bsrc,
                                                 const float* __restrict__ bdst) {
    __shared__ float    sA [2][64 * 16];
    __shared__ unsigned sBb[2][2048];
    __shared__ unsigned sBs[2][2048];

    const int t    = threadIdx.x;
    const int wid  = t >> 5;
    const int lane = t & 31;
    const int g    = lane >> 2;
    const int tq   = lane & 3;
    const int row0 = blockIdx.x * MT;

    const int mb    = (wid & 3) * 16;
    const int nbase = (wid >> 2) * 128;

    float acc[16][4];
    #pragma unroll
    for (int nt = 0; nt < 16; nt++)
        #pragma unroll
        for (int q = 0; q < 4; q++) acc[nt][q] = 0.f;

    const int ar = t >> 2;
    const int aq = t & 3;
    const int gr = row0 + ar;
    const float* aSrcBase = h + (size_t)gr * INDIM + aq * 4;
    const int aBytes = (gr < NND) ? 16 : 0;
    const uint32_t aDst0 = smem_u32(&sA[0][0]) + (uint32_t)(ar * 64 + ((aq ^ (ar & 3)) * 16));
    const int aStage = 64 * 16 * 4;

    const int bn  = t;
    const int bsw = (bn >> 2) & 1;
    const uint32_t bbDst0 = smem_u32(&sBb[0][0]) + (uint32_t)(bn * 32 + (0 ^ bsw) * 16);
    const uint32_t bbDst1 = smem_u32(&sBb[0][0]) + (uint32_t)(bn * 32 + (1 ^ bsw) * 16);
    const uint32_t bsDst0 = smem_u32(&sBs[0][0]) + (uint32_t)(bn * 32 + (0 ^ bsw) * 16);
    const uint32_t bsDst1 = smem_u32(&sBs[0][0]) + (uint32_t)(bn * 32 + (1 ^ bsw) * 16);
    const int bStage = 2048 * 4;

    auto issue = [&](int ch, int s) {
        if (ch < 16) {
            cp16(aDst0 + s * aStage, aSrcBase + ch * 16, aBytes);
            const unsigned* wb = g_Wtb32 + ch * 2048 + bn * 8;
            const unsigned* ws = g_Wts32 + ch * 2048 + bn * 8;
            cp16(bbDst0 + s * bStage, wb,     16);
            cp16(bbDst1 + s * bStage, wb + 4, 16);
            cp16(bsDst0 + s * bStage, ws,     16);
            cp16(bsDst1 + s * bStage, ws + 4, 16);
        }
        CP_COMMIT();
    };

    issue(0, 0);
    issue(1, 1);

    const int rlo = mb + g, rhi = rlo + 8;
    const int klo = 2 * tq;
    const int alo0 = rlo * 16 + (((klo >> 2)    ) ^ (rlo & 3)) * 4 + (klo & 3);
    const int alo8 = rlo * 16 + (((klo >> 2) + 2) ^ (rlo & 3)) * 4 + (klo & 3);
    const int ahi0 = rhi * 16 + (((klo >> 2)    ) ^ (rhi & 3)) * 4 + (klo & 3);
    const int ahi8 = rhi * 16 + (((klo >> 2) + 2) ^ (rhi & 3)) * 4 + (klo & 3);

    for (int ch = 0; ch < 16; ch++) {
        const int s = ch & 1;
        CP_WAIT1();
        __syncthreads();

        const float* A = sA[s];
        float2 vlo0 = *reinterpret_cast<const float2*>(A + alo0);
        float2 vhi0 = *reinterpret_cast<const float2*>(A + ahi0);
        float2 vlo8 = *reinterpret_cast<const float2*>(A + alo8);
        float2 vhi8 = *reinterpret_cast<const float2*>(A + ahi8);
        float b;
        unsigned ab[4], ar_[4];
        b = bf_big(vlo0.x); float b2 = bf_big(vlo0.y);
        ab[0] = bfpair(b, b2);          ar_[0] = bfpair(vlo0.x - b, vlo0.y - b2);
        b = bf_big(vhi0.x); b2 = bf_big(vhi0.y);
        ab[1] = bfpair(b, b2);          ar_[1] = bfpair(vhi0.x - b, vhi0.y - b2);
        b = bf_big(vlo8.x); b2 = bf_big(vlo8.y);
        ab[2] = bfpair(b, b2);          ar_[2] = bfpair(vlo8.x - b, vlo8.y - b2);
        b = bf_big(vhi8.x); b2 = bf_big(vhi8.y);
        ab[3] = bfpair(b, b2);          ar_[3] = bfpair(vhi8.x - b, vhi8.y - b2);

        const unsigned* Bb = sBb[s];
        const unsigned* Bs = sBs[s];
        #pragma unroll
        for (int nt = 0; nt < 16; nt++) {
            int n   = nbase + nt * 8 + g;
            int qsw = (n >> 2) & 1;
            int i0  = n * 8 + qsw * 4 + tq;
            int i1  = n * 8 + (1 ^ qsw) * 4 + tq;
            unsigned bb[2] = {Bb[i0], Bb[i1]};
            unsigned bs[2] = {Bs[i0], Bs[i1]};
            mma16816(acc[nt], ab,  bb);
            mma16816(acc[nt], ar_, bb);
            mma16816(acc[nt], ab,  bs);
        }
        __syncthreads();
        issue(ch + 2, s);
    }

    const int grl = row0 + mb + g;
    const int grh = grl + 8;
    #pragma unroll
    for (int nt = 0; nt < 16; nt++) {
        int col = nbase + nt * 8 + 2 * tq;
        float* outp = (col < HD) ? g_el : g_er;
        const float* bias = (col < HD) ? bsrc : bdst;
        int cc = col & (HD - 1);
        float2 bv = *reinterpret_cast<const float2*>(bias + cc);
        if (grl < NND)
            *reinterpret_cast<float2*>(outp + (size_t)grl * HD + cc) =
                make_float2(acc[nt][0] + bv.x, acc[nt][1] + bv.y);
        if (grh < NND)
            *reinterpret_cast<float2*>(outp + (size_t)grh * HD + cc) =
                make_float2(acc[nt][2] + bv.x, acc[nt][3] + bv.y);
    }
}

// ---------------- CSR build ----------------
__global__ void k_zero() {
    int i = blockIdx.x * blockDim.x + threadIdx.x;
    if (i < NND) g_cnt[i] = 0;
}
__global__ void k_hist(const int* __restrict__ dst) {
    int e = blockIdx.x * blockDim.x + threadIdx.x;
    if (e < NE) atomicAdd(&g_cnt[dst[e]], 1);
}

__global__ void __launch_bounds__(256) k_bsum() {
    __shared__ int s[8];
    int idx = blockIdx.x * 256 + threadIdx.x;
    int v = (idx < NND) ? g_cnt[idx] : 0;
    #pragma unroll
    for (int o = 16; o > 0; o >>= 1) v += __shfl_xor_sync(0xffffffffu, v, o);
    if ((threadIdx.x & 31) == 0) s[threadIdx.x >> 5] = v;
    __syncthreads();
    if (threadIdx.x < 8) {
        int w = s[threadIdx.x];
        #pragma unroll
        for (int o = 4; o > 0; o >>= 1) w += __shfl_xor_sync(0xffu, w, o);
        if (threadIdx.x == 0) g_bsum[blockIdx.x] = w;
    }
}

__global__ void __launch_bounds__(256) k_bscan() {
    __shared__ int s[256];
    int t = threadIdx.x;
    int v = (t < NB) ? g_bsum[t] : 0;
    s[t] = v;
    __syncthreads();
    #pragma unroll
    for (int o = 1; o < 256; o <<= 1) {
        int u = (t >= o) ? s[t - o] : 0;
        __syncthreads();
        s[t] += u;
        __syncthreads();
    }
    if (t < NB) g_bpref[t] = s[t] - v;
    if (t == 0) g_off[NND] = NE;
}

__global__ void __launch_bounds__(256) k_offsets() {
    __shared__ int s[256];
    int t   = threadIdx.x;
    int idx = blockIdx.x * 256 + t;
    int v   = (idx < NND) ? g_cnt[idx] : 0;
    s[t] = v;
    __syncthreads();
    #pragma unroll
    for (int o = 1; o < 256; o <<= 1) {
        int u = (t >= o) ? s[t - o] : 0;
        __syncthreads();
        s[t] += u;
        __syncthreads();
    }
    if (idx < NND) {
        int off = g_bpref[blockIdx.x] + s[t] - v;
        g_off[idx]    = off;
        g_cursor[idx] = off;
    }
}

__global__ void k_bucket(const int* __restrict__ src, const int* __restrict__ dst) {
    int e = blockIdx.x * blockDim.x + threadIdx.x;
    if (e >= NE) return;
    int d = dst[e];
    int p = atomicAdd(&g_cursor[d], 1);
    g_pairs[p] = make_int2(e, src[e]);
}

// ---------------- K_dst: 2 warps per dst; R15 inner loop + softmax merge ------
// block = 256 thr = 8 warps = 4 dsts. grid = 12500 (4*12500 = 50000 = NND).
__global__ void __launch_bounds__(256) k_dst(const float* __restrict__ attn,
                                             float* __restrict__ out) {
    __shared__ float sm[4][32][6];   // partner (half 1) partial: m, denom, acc4

    const int lane = threadIdx.x & 31;
    const int half = (threadIdx.x >> 5) & 1;
    const int pi   = threadIdx.x >> 6;           // 0..3 dst slot in block
    const int d    = blockIdx.x * 4 + pi;        // < 50000 always

    const int start0 = g_off[d];
    const int cnt0   = g_off[d + 1] - start0;
    const int hsz    = (cnt0 + 1) >> 1;
    const int start  = half ? (start0 + hsz) : start0;
    const int cnt    = half ? (cnt0 - hsz) : hsz;

    const float4 er4 = reinterpret_cast<const float4*>(g_er + (size_t)d * HD)[lane];
    const float4 w4  = reinterpret_cast<const float4*>(attn)[lane];

    float m = -1e30f, denom = 0.f;
    float4 acc = make_float4(0.f, 0.f, 0.f, 0.f);

    // R15 dual-edge ILP loop over this warp's half
    int2   p0, p1;
    float4 a0, a1;
    if (cnt > 0) {
        p0 = g_pairs[start];
        a0 = reinterpret_cast<const float4*>(g_el + (size_t)p0.y * HD)[lane];
    }
    if (cnt > 1) {
        p1 = g_pairs[start + 1];
        a1 = reinterpret_cast<const float4*>(g_el + (size_t)p1.y * HD)[lane];
    }

    int i = 0;
    for (; i + 1 < cnt; i += 2) {
        int2 q0, q1; float4 b0, b1;
        if (i + 2 < cnt) {
            q0 = g_pairs[start + i + 2];
            b0 = reinterpret_cast<const float4*>(g_el + (size_t)q0.y * HD)[lane];
        }
        if (i + 3 < cnt) {
            q1 = g_pairs[start + i + 3];
            b1 = reinterpret_cast<const float4*>(g_el + (size_t)q1.y * HD)[lane];
        }

        float s0 = lrelu(a0.x + er4.x) * w4.x + lrelu(a0.y + er4.y) * w4.y +
                   lrelu(a0.z + er4.z) * w4.z + lrelu(a0.w + er4.w) * w4.w;
        float s1 = lrelu(a1.x + er4.x) * w4.x + lrelu(a1.y + er4.y) * w4.y +
                   lrelu(a1.z + er4.z) * w4.z + lrelu(a1.w + er4.w) * w4.w;
        s0 += __shfl_xor_sync(0xffffffffu, s0, 1);
        s1 += __shfl_xor_sync(0xffffffffu, s1, 1);
        s0 += __shfl_xor_sync(0xffffffffu, s0, 2);
        s1 += __shfl_xor_sync(0xffffffffu, s1, 2);
        s0 += __shfl_xor_sync(0xffffffffu, s0, 4);
        s1 += __shfl_xor_sync(0xffffffffu, s1, 4);

        if ((lane & 7) == 0) {
            g_scores[(size_t)p0.x * NH + (lane >> 3)] = s0;
            g_scores[(size_t)p1.x * NH + (lane >> 3)] = s1;
        }

        {
            float delta = s0 - m;
            bool  up    = delta > 0.f;
            float e     = __expf(up ? -delta : delta);
            float scl   = up ? e : 1.f;
            float ex    = up ? 1.f : e;
            if (up) m = s0;
            denom = denom * scl + ex;
            acc.x = fmaf(acc.x, scl, ex * a0.x);
            acc.y = fmaf(acc.y, scl, ex * a0.y);
            acc.z = fmaf(acc.z, scl, ex * a0.z);
            acc.w = fmaf(acc.w, scl, ex * a0.w);
        }
        {
            float delta = s1 - m;
            bool  up    = delta > 0.f;
            float e     = __expf(up ? -delta : delta);
            float scl   = up ? e : 1.f;
            float ex    = up ? 1.f : e;
            if (up) m = s1;
            denom = denom * scl + ex;
            acc.x = fmaf(acc.x, scl, ex * a1.x);
            acc.y = fmaf(acc.y, scl, ex * a1.y);
            acc.z = fmaf(acc.z, scl, ex * a1.z);
            acc.w = fmaf(acc.w, scl, ex * a1.w);
        }

        p0 = q0; a0 = b0;
        p1 = q1; a1 = b1;
    }
    if (i < cnt) {
        float s0 = lrelu(a0.x + er4.x) * w4.x + lrelu(a0.y + er4.y) * w4.y +
                   lrelu(a0.z + er4.z) * w4.z + lrelu(a0.w + er4.w) * w4.w;
        s0 += __shfl_xor_sync(0xffffffffu, s0, 1);
        s0 += __shfl_xor_sync(0xffffffffu, s0, 2);
        s0 += __shfl_xor_sync(0xffffffffu, s0, 4);
        if ((lane & 7) == 0)
            g_scores[(size_t)p0.x * NH + (lane >> 3)] = s0;
        float delta = s0 - m;
        bool  up    = delta > 0.f;
        float e     = __expf(up ? -delta : delta);
        float scl   = up ? e : 1.f;
        float ex    = up ? 1.f : e;
        if (up) m = s0;
        denom = denom * scl + ex;
        acc.x = fmaf(acc.x, scl, ex * a0.x);
        acc.y = fmaf(acc.y, scl, ex * a0.y);
        acc.z = fmaf(acc.z, scl, ex * a0.z);
        acc.w = fmaf(acc.w, scl, ex * a0.w);
    }

    // ---- merge the two halves ----
    if (half == 1) {
        sm[pi][lane][0] = m;
        sm[pi][lane][1] = denom;
        sm[pi][lane][2] = acc.x;
        sm[pi][lane][3] = acc.y;
        sm[pi][lane][4] = acc.z;
        sm[pi][lane][5] = acc.w;
    }
    __syncthreads();
    if (half == 0) {
        float m1  = sm[pi][lane][0];
        float dn1 = sm[pi][lane][1];
        float mm  = fmaxf(m, m1);
        float f0  = __expf(m - mm);
        float f1  = __expf(m1 - mm);
        float den = denom * f0 + dn1 * f1;
        float ox = acc.x * f0 + sm[pi][lane][2] * f1;
        float oy = acc.y * f0 + sm[pi][lane][3] * f1;
        float oz = acc.z * f0 + sm[pi][lane][4] * f1;
        float ow = acc.w * f0 + sm[pi][lane][5] * f1;

        float rden = (cnt0 > 0) ? 1.f / den : 0.f;
        reinterpret_cast<float4*>(out + (size_t)d * HD)[lane] =
            make_float4(ox * rden, oy * rden, oz * rden, ow * rden);
        if ((lane & 7) == 0)
            g_mden[(size_t)d * NH + (lane >> 3)] = make_float2(mm, rden);
    }
}

// ---------------- K_attn: flat edge-parallel attention weights ----------------
__global__ void __launch_bounds__(256) k_attn(const int* __restrict__ dst,
                                              float* __restrict__ out_a) {
    int i = blockIdx.x * 256 + threadIdx.x;
    if (i >= NE * NH) return;
    int e = i >> 2;
    int d = __ldg(&dst[e]);
    float2 md = g_mden[(size_t)d * NH + (i & 3)];
    out_a[i] = __expf(g_scores[i] - md.x) * md.y;
}

// ---------------- launch ----------------
extern "C" void kernel_launch(void* const* d_in, const int* in_sizes, int n_in,
                              void* d_out, int out_size) {
    const float* h     = (const float*)d_in[0];
    const int*   src   = (const int*)  d_in[1];
    const int*   dst   = (const int*)  d_in[2];
    const float* W_src = (const float*)d_in[3];
    const float* b_src = (const float*)d_in[4];
    const float* W_dst = (const float*)d_in[5];
    const float* b_dst = (const float*)d_in[6];
    const float* attn  = (const float*)d_in[7];

    float* out   = (float*)d_out;
    float* out_a = out + (size_t)NND * HD;
    int writeA   = (out_size >= NND * HD + NE * NH) ? 1 : 0;

    cudaStream_t s2;
    cudaEvent_t  evFork, evJoin;
    cudaStreamCreateWithFlags(&s2, cudaStreamNonBlocking);
    cudaEventCreateWithFlags(&evFork, cudaEventDisableTiming);
    cudaEventCreateWithFlags(&evJoin, cudaEventDisableTiming);

    cudaEventRecord(evFork, 0);
    cudaStreamWaitEvent(s2, evFork, 0);

    // side stream: start of CSR chain
    k_zero   <<<(NND + 255) / 256, 256, 0, s2>>>();
    k_hist   <<<(NE + 255) / 256, 256, 0, s2>>>(dst);
    // main stream: W prep, then GEMM (launch #4 for the ncu skip-window)
    k_wprep<<<256, 128>>>(W_src, W_dst);
    k_gemm <<<NGRID, 256>>>(h, b_src, b_dst);
    // side stream: rest of CSR chain
    k_bsum   <<<NB, 256, 0, s2>>>();
    k_bscan  <<<1, 256, 0, s2>>>();
    k_offsets<<<NB, 256, 0, s2>>>();
    k_bucket <<<(NE + 255) / 256, 256, 0, s2>>>(src, dst);
    cudaEventRecord(evJoin, s2);

    cudaStreamWaitEvent(0, evJoin, 0);
    k_dst<<<(NND + 3) / 4, 256>>>(attn, out);
    if (writeA)
        k_attn<<<(NE * NH + 255) / 256, 256>>>(dst, out_a);
}